// round 14
// baseline (speedup 1.0000x reference)
#include <cuda_runtime.h>
#include <cuda_fp16.h>
#include <cstdint>
#include <cstddef>

// ---------------------------------------------------------------------------
// Problem constants
// ---------------------------------------------------------------------------
#define B_DIM 4
#define S_DIM 2048
#define V_DIM 32000
#define K_DIM 512            // 2*D
#define D_DIM 256
#define M_DIM 8192           // B*S
#define LUT_N 4096

// exact-double constants rounded to f32
#define PHI_F   1.6180339887498949f          // (1+sqrt5)/2
#define CINV_F  651.8986469044033f           // 4096 / (2*pi)
#define GRID_F  0.0015339807878856412f       // (2*pi) / 4096

// GEMM tiling: CTA tile 256x128, 512 threads (16 warps), warp tile 64x32
#define TM 256
#define TN 128
#define KC 64                // k elements per stage = 128 bytes fp16
#define NKC 8                // 512 / 64
#define NSTAGE 3
#define NTHREADS 512

#define NSCAN 32             // scan blocks (8 per batch, 32 chains each)
#define NTILE_N (V_DIM / TN) // 250
#define NTILE_M (M_DIM / TM) // 32

// scratch (device globals allowed; runtime alloc is not)
static __device__ __align__(256) __half g_A[(size_t)M_DIM * K_DIM];
static __device__ __align__(256) __half g_B[(size_t)V_DIM * K_DIM];
static __device__ int g_prog[NSCAN];   // per-scan-block step progress

// ---------------------------------------------------------------------------
// PTX helpers (base-arch only: cp.async, ldmatrix, mma.sync)
// ---------------------------------------------------------------------------
__device__ __forceinline__ uint32_t smem_u32(const void* p) {
    return (uint32_t)__cvta_generic_to_shared(p);
}
__device__ __forceinline__ void cp_async16(uint32_t dst, const void* src) {
    asm volatile("cp.async.cg.shared.global [%0], [%1], 16;"
                 :: "r"(dst), "l"(src) : "memory");
}
#define CP_COMMIT() asm volatile("cp.async.commit_group;" ::: "memory")
#define CP_WAIT1()  asm volatile("cp.async.wait_group 1;" ::: "memory")
#define FENCE_PROXY_ASYNC() asm volatile("fence.proxy.async;" ::: "memory")

__device__ __forceinline__ void ldmatrix_x4(uint32_t* r, uint32_t addr) {
    asm volatile("ldmatrix.sync.aligned.m8n8.x4.shared.b16 {%0,%1,%2,%3}, [%4];"
                 : "=r"(r[0]), "=r"(r[1]), "=r"(r[2]), "=r"(r[3]) : "r"(addr));
}

__device__ __forceinline__ void mma16816(float* c, const uint32_t* a,
                                         uint32_t b0, uint32_t b1) {
    asm volatile(
        "mma.sync.aligned.m16n8k16.row.col.f32.f16.f16.f32 "
        "{%0,%1,%2,%3}, {%4,%5,%6,%7}, {%8,%9}, {%0,%1,%2,%3};"
        : "+f"(c[0]), "+f"(c[1]), "+f"(c[2]), "+f"(c[3])
        : "r"(a[0]), "r"(a[1]), "r"(a[2]), "r"(a[3]), "r"(b0), "r"(b1));
}

__device__ __forceinline__ uint32_t sw128(uint32_t off) {
    return off ^ ((off >> 3) & 0x70);
}

__device__ __forceinline__ int ld_acq(const int* p) {
    int v;
    asm volatile("ld.acquire.gpu.global.b32 %0, [%1];" : "=r"(v) : "l"(p));
    return v;
}
__device__ __forceinline__ void st_rel(int* p, int v) {
    asm volatile("st.release.gpu.global.b32 [%0], %1;" :: "l"(p), "r"(v) : "memory");
}

// Guard-free correctly-rounded fp32 division (Markstein). Valid for normal
// a, b with no overflow in intermediates — here |a|<=1, b in [1, ~3].
__device__ __forceinline__ float div_rn_fast(float a, float b) {
    float r;
    asm("rcp.approx.f32 %0, %1;" : "=f"(r) : "f"(b));
    float e = __fmaf_rn(-b, r, 1.0f);
    r = __fmaf_rn(r, e, r);
    e = __fmaf_rn(-b, r, 1.0f);
    r = __fmaf_rn(r, e, r);
    float q = __fmul_rn(a, r);
    float rem = __fmaf_rn(-b, q, a);
    return __fmaf_rn(rem, r, q);
}

// ---------------------------------------------------------------------------
// Kernel A: proj fp32 -> fp16, plus progress-flag reset (runs before fused)
// ---------------------------------------------------------------------------
__global__ void rin_conv_kernel(const float* __restrict__ p) {
    if (blockIdx.x == 0 && threadIdx.x < NSCAN) g_prog[threadIdx.x] = 0;
    size_t i = ((size_t)blockIdx.x * blockDim.x + threadIdx.x) * 4;
    if (i < (size_t)V_DIM * K_DIM) {
        float4 v = *(const float4*)(p + i);
        __half2 h0 = __floats2half2_rn(v.x, v.y);
        __half2 h1 = __floats2half2_rn(v.z, v.w);
        uint2 st;
        st.x = *(uint32_t*)&h0;
        st.y = *(uint32_t*)&h1;
        *(uint2*)(g_B + i) = st;
    }
}

// ---------------------------------------------------------------------------
// Fused kernel: bids 0..31 = scan producers (R9-proven logic; block exits
// after the scan so the SM rejoins the GEMM wave pool). bids 32.. = GEMM
// consumers: 512 threads, CTA tile 256x128, 16 warps (4/SMSP), warp tile
// 64x32 (identical inner loop to the proven config), 3-stage cp.async ring.
// ---------------------------------------------------------------------------
#define A_TILE  32768                 // 256 rows * 128B
#define B_TILE  16384                 // 128 rows * 128B
#define STAGE_SZ (A_TILE + B_TILE)    // 49152
#define SM_TOTAL (NSTAGE * STAGE_SZ)  // 147456 per CTA

#define PF 8

__device__ __forceinline__ void load_stage_A(uint32_t sb, int stage, int kc,
                                             int m0, int tid) {
    const __half* Ag = g_A + (size_t)m0 * K_DIM + kc * KC;
    uint32_t abase = sb + stage * STAGE_SZ;
#pragma unroll
    for (int it = 0; it < 4; it++) {                // A: 2048 16B units
        int u = tid + it * NTHREADS;
        int r = u >> 3, c = u & 7;
        uint32_t off = (uint32_t)(r * 128 + c * 16);
        cp_async16(abase + sw128(off), Ag + (size_t)r * K_DIM + c * 8);
    }
}

__device__ __forceinline__ void load_stage_B(uint32_t sb, int stage, int kc,
                                             int n0, int tid) {
    const __half* Bg = g_B + (size_t)n0 * K_DIM + kc * KC;
    uint32_t bbase = sb + stage * STAGE_SZ + A_TILE;
#pragma unroll
    for (int it = 0; it < 2; it++) {                // B: 1024 16B units
        int u = tid + it * NTHREADS;
        int r = u >> 3, c = u & 7;
        uint32_t off = (uint32_t)(r * 128 + c * 16);
        cp_async16(bbase + sw128(off), Bg + (size_t)r * K_DIM + c * 8);
    }
}

__global__ void __launch_bounds__(NTHREADS, 1) rin_fused_kernel(
        const int* __restrict__ ids, const float* __restrict__ emb,
        float* __restrict__ out, const float* __restrict__ bias) {
    extern __shared__ char smem[];
    const int tid = threadIdx.x;

    if (blockIdx.x < NSCAN) {
        // ---------------- scan producer (R9-proven logic) ----------------
        float* s_sin = (float*)smem;
        float* s_cos = s_sin + LUT_N;
        for (int i = tid; i < LUT_N; i += NTHREADS) {
            float g = __fmul_rn((float)i, GRID_F);
            s_sin[i] = sinf(g);
            s_cos[i] = cosf(g);
        }
        __syncthreads();
        if (tid >= 32) return;                 // only warp 0 runs chains

        const int bid = blockIdx.x;
        const int b = bid >> 3;
        const int d = ((bid & 7) << 5) + tid;

        const int* rid = ids + b * S_DIM;
        float hr = 0.0f, hi = 0.0f;

        float wp[PF], bp[PF];
#pragma unroll
        for (int j = 0; j < PF; j++) {
            int id = __ldg(rid + j);
            wp[j] = __ldg(emb + (size_t)id * K_DIM + d);
            bp[j] = __ldg(emb + (size_t)id * K_DIM + D_DIM + d);
        }

        __half* arow = g_A + (size_t)b * S_DIM * K_DIM + d;

        for (int s0 = 0; s0 < S_DIM; s0 += PF) {
#pragma unroll
            for (int j = 0; j < PF; j++) {
                int s = s0 + j;
                float w = wp[j];
                float bt = bp[j];
                if (s + PF < S_DIM) {
                    int id = __ldg(rid + s + PF);
                    wp[j] = __ldg(emb + (size_t)id * K_DIM + d);
                    bp[j] = __ldg(emb + (size_t)id * K_DIM + D_DIM + d);
                }
                float lam = __fadd_rn(1.0f, fabsf(w));
                float tp  = __fmul_rn((float)s, PHI_F);
                float tr  = __fadd_rn(__fadd_rn(div_rn_fast(hr, lam), bt), tp);
                float ti  = __fadd_rn(__fadd_rn(div_rn_fast(hi, lam), bt), tp);
                int ir = __float2int_rd(__fmul_rn(tr, CINV_F)) & (LUT_N - 1);
                int ii = __float2int_rd(__fmul_rn(ti, CINV_F)) & (LUT_N - 1);
                float sr = s_sin[ir], cr = s_cos[ir];
                float si = s_sin[ii], ci = s_cos[ii];
                float nhr = __fsub_rn(__fmul_rn(cr, ci), __fmul_rn(sr, si));
                float nhi = __fadd_rn(__fmul_rn(cr, si), __fmul_rn(sr, ci));
                hr = nhr;
                hi = nhi;
                arow[(size_t)s * K_DIM]         = __float2half_rn(nhr);
                arow[(size_t)s * K_DIM + D_DIM] = __float2half_rn(nhi);
            }
            if (((s0 + PF) & 127) == 0) {       // publish every 128 steps
                __threadfence();
                __syncwarp();
                if (tid == 0) st_rel(&g_prog[bid], s0 + PF);
            }
        }
        return;
    }

    // --------------------------- GEMM consumer ---------------------------
    uint32_t sb = smem_u32(smem);
    const int g = blockIdx.x - NSCAN;
    // step-major, batch-minor tile order: matches scan production order
    const int mt = g / NTILE_N;              // 0..31
    const int jj_step = mt >> 2;             // step group 0..7 (256 rows each)
    const int bb = mt & 3;                   // batch
    const int m0 = bb * S_DIM + jj_step * TM;
    const int n0 = (g % NTILE_N) * TN;
    const int lane = tid & 31;
    const int wid = tid >> 5;                // 0..15
    const int wm = wid & 3;                  // 4 M slabs of 64
    const int wn = wid >> 2;                 // 4 N slabs of 32

    // B is ready (stream-ordered): issue B transfers for stages 0,1 now so
    // they overlap the A-availability wait below.
    load_stage_B(sb, 0, 0, n0, tid);
    load_stage_B(sb, 1, 1, n0, tid);

    // wait until this tile's 256 A-rows are produced by all 8 scan blocks of bb
    {
        const int s_end = jj_step * TM + TM;
        if (tid < 8) {
            const int* fp = &g_prog[bb * 8 + tid];
            while (ld_acq(fp) < s_end) __nanosleep(128);
        }
        __syncthreads();
        // Bridge generic-proxy release chain (scan's st.global + fence) to the
        // async-proxy cp.async reads of g_A below.
        FENCE_PROXY_ASYNC();
    }

    float acc[4][4][4];
#pragma unroll
    for (int i = 0; i < 4; i++)
#pragma unroll
        for (int j = 0; j < 4; j++)
#pragma unroll
            for (int k = 0; k < 4; k++) acc[i][j][k] = 0.0f;

    load_stage_A(sb, 0, 0, m0, tid);
    CP_COMMIT();                    // group0 = {B0, B1, A0}
    load_stage_A(sb, 1, 1, m0, tid);
    CP_COMMIT();                    // group1 = {A1}

    const int a_row  = wm * 64 + (lane & 15);
    const int a_sega = (lane >> 4) * 16;
    const int b_row  = wn * 32 + (lane & 7) + ((lane >> 4) << 3);
    const int b_sega = ((lane >> 3) & 1) * 16;

    int buf = 0;
    for (int kc = 0; kc < NKC; kc++) {
        CP_WAIT1();                 // stage kc data complete
        __syncthreads();
        if (kc + 2 < NKC) {
            int st2 = (buf + 2 >= NSTAGE) ? buf + 2 - NSTAGE : buf + 2;
            load_stage_B(sb, st2, kc + 2, n0, tid);
            load_stage_A(sb, st2, kc + 2, m0, tid);
            CP_COMMIT();
        }

        const uint32_t abase = sb + buf * STAGE_SZ;
        const uint32_t bbase = abase + A_TILE;
#pragma unroll
        for (int ks = 0; ks < 4; ks++) {
            uint32_t ar[4][4];
#pragma unroll
            for (int i = 0; i < 4; i++) {
                uint32_t off = (uint32_t)((a_row + i * 16) * 128 + ks * 32 + a_sega);
                ldmatrix_x4(ar[i], abase + sw128(off));
            }
            uint32_t br[2][4];
#pragma unroll
            for (int j = 0; j < 2; j++) {
                uint32_t off = (uint32_t)((b_row + j * 16) * 128 + ks * 32 + b_sega);
                ldmatrix_x4(br[j], bbase + sw128(off));
            }
#pragma unroll
            for (int i = 0; i < 4; i++)
#pragma unroll
                for (int j2 = 0; j2 < 4; j2++)
                    mma16816(acc[i][j2], ar[i],
                             br[j2 >> 1][(j2 & 1) * 2],
                             br[j2 >> 1][(j2 & 1) * 2 + 1]);
        }
        buf = (buf + 1 == NSTAGE) ? 0 : buf + 1;
    }

    const int ncol0 = n0 + wn * 32;
#pragma unroll
    for (int i = 0; i < 4; i++) {
        int row = m0 + wm * 64 + i * 16 + (lane >> 2);
        float* o0 = out + (size_t)row * V_DIM + ncol0;
        float* o1 = o0 + (size_t)8 * V_DIM;
#pragma unroll
        for (int j2 = 0; j2 < 4; j2++) {
            int col = j2 * 8 + (lane & 3) * 2;
            float bx = __ldg(bias + ncol0 + col);
            float by = __ldg(bias + ncol0 + col + 1);
            float2 v0 = make_float2(acc[i][j2][0] + bx, acc[i][j2][1] + by);
            float2 v1 = make_float2(acc[i][j2][2] + bx, acc[i][j2][3] + by);
            *(float2*)(o0 + col) = v0;
            *(float2*)(o1 + col) = v1;
        }
    }
}

// ---------------------------------------------------------------------------
// launch
// ---------------------------------------------------------------------------
extern "C" void kernel_launch(void* const* d_in, const int* in_sizes, int n_in,
                              void* d_out, int out_size) {
    const int*   ids  = (const int*)d_in[0];
    const float* emb  = (const float*)d_in[1];
    const float* proj = (const float*)d_in[2];
    const float* bias = (const float*)d_in[3];
    float* out = (float*)d_out;

    cudaFuncSetAttribute(rin_fused_kernel,
                         cudaFuncAttributeMaxDynamicSharedMemorySize, SM_TOTAL);

    rin_conv_kernel<<<(V_DIM * K_DIM / 4 + 255) / 256, 256>>>(proj);
    rin_fused_kernel<<<NSCAN + NTILE_M * NTILE_N, NTHREADS, SM_TOTAL>>>(
        ids, emb, out, bias);
}

// round 15
// speedup vs baseline: 1.2044x; 1.2044x over previous
#include <cuda_runtime.h>
#include <cuda_fp16.h>
#include <cstdint>
#include <cstddef>

// ---------------------------------------------------------------------------
// Problem constants
// ---------------------------------------------------------------------------
#define B_DIM 4
#define S_DIM 2048
#define V_DIM 32000
#define K_DIM 512            // 2*D
#define D_DIM 256
#define M_DIM 8192           // B*S
#define LUT_N 4096

// exact-double constants rounded to f32
#define PHI_F   1.6180339887498949f          // (1+sqrt5)/2
#define CINV_F  651.8986469044033f           // 4096 / (2*pi)
#define GRID_F  0.0015339807878856412f       // (2*pi) / 4096

// GEMM tiling: CTA tile 128x128, 128 threads (4 warps), warp tile 64x64
#define TM 128
#define TN 128
#define KC 64                // k elements per stage = 128 bytes fp16
#define NKC 8                // 512 / 64
#define NSTAGE 3
#define NTHREADS 128

#define NSCAN 32             // scan blocks (8 per batch, 32 chains each)
#define NTILE_N (V_DIM / TN) // 250
#define NTILE_M (M_DIM / TM) // 64

// scratch (device globals allowed; runtime alloc is not)
static __device__ __align__(256) __half g_A[(size_t)M_DIM * K_DIM];
static __device__ __align__(256) __half g_B[(size_t)V_DIM * K_DIM];
static __device__ int g_prog[NSCAN];   // per-scan-block step progress

// ---------------------------------------------------------------------------
// PTX helpers (base-arch only: cp.async, ldmatrix, mma.sync)
// ---------------------------------------------------------------------------
__device__ __forceinline__ uint32_t smem_u32(const void* p) {
    return (uint32_t)__cvta_generic_to_shared(p);
}
__device__ __forceinline__ void cp_async16(uint32_t dst, const void* src) {
    asm volatile("cp.async.cg.shared.global [%0], [%1], 16;"
                 :: "r"(dst), "l"(src) : "memory");
}
#define CP_COMMIT() asm volatile("cp.async.commit_group;" ::: "memory")
#define CP_WAIT1()  asm volatile("cp.async.wait_group 1;" ::: "memory")
#define FENCE_PROXY_ASYNC() asm volatile("fence.proxy.async;" ::: "memory")

__device__ __forceinline__ void ldmatrix_x4(uint32_t* r, uint32_t addr) {
    asm volatile("ldmatrix.sync.aligned.m8n8.x4.shared.b16 {%0,%1,%2,%3}, [%4];"
                 : "=r"(r[0]), "=r"(r[1]), "=r"(r[2]), "=r"(r[3]) : "r"(addr));
}

__device__ __forceinline__ void mma16816(float* c, const uint32_t* a,
                                         uint32_t b0, uint32_t b1) {
    asm volatile(
        "mma.sync.aligned.m16n8k16.row.col.f32.f16.f16.f32 "
        "{%0,%1,%2,%3}, {%4,%5,%6,%7}, {%8,%9}, {%0,%1,%2,%3};"
        : "+f"(c[0]), "+f"(c[1]), "+f"(c[2]), "+f"(c[3])
        : "r"(a[0]), "r"(a[1]), "r"(a[2]), "r"(a[3]), "r"(b0), "r"(b1));
}

__device__ __forceinline__ uint32_t sw128(uint32_t off) {
    return off ^ ((off >> 3) & 0x70);
}

__device__ __forceinline__ int ld_acq(const int* p) {
    int v;
    asm volatile("ld.acquire.gpu.global.b32 %0, [%1];" : "=r"(v) : "l"(p));
    return v;
}
__device__ __forceinline__ void st_rel(int* p, int v) {
    asm volatile("st.release.gpu.global.b32 [%0], %1;" :: "l"(p), "r"(v) : "memory");
}

// Guard-free correctly-rounded fp32 division (Markstein). Valid for normal
// a, b with no overflow in intermediates — here |a|<=1, b in [1, ~3].
__device__ __forceinline__ float div_rn_fast(float a, float b) {
    float r;
    asm("rcp.approx.f32 %0, %1;" : "=f"(r) : "f"(b));
    float e = __fmaf_rn(-b, r, 1.0f);
    r = __fmaf_rn(r, e, r);
    e = __fmaf_rn(-b, r, 1.0f);
    r = __fmaf_rn(r, e, r);
    float q = __fmul_rn(a, r);
    float rem = __fmaf_rn(-b, q, a);
    return __fmaf_rn(rem, r, q);
}

// ---------------------------------------------------------------------------
// Kernel A: proj fp32 -> fp16, plus progress-flag reset (runs before fused)
// ---------------------------------------------------------------------------
__global__ void rin_conv_kernel(const float* __restrict__ p) {
    if (blockIdx.x == 0 && threadIdx.x < NSCAN) g_prog[threadIdx.x] = 0;
    size_t i = ((size_t)blockIdx.x * blockDim.x + threadIdx.x) * 4;
    if (i < (size_t)V_DIM * K_DIM) {
        float4 v = *(const float4*)(p + i);
        __half2 h0 = __floats2half2_rn(v.x, v.y);
        __half2 h1 = __floats2half2_rn(v.z, v.w);
        uint2 st;
        st.x = *(uint32_t*)&h0;
        st.y = *(uint32_t*)&h1;
        *(uint2*)(g_B + i) = st;
    }
}

// ---------------------------------------------------------------------------
// Fused kernel: bids 0..31 = scan producers (R9-proven logic), bids 32.. =
// GEMM consumers. 128 threads/CTA, 2 CTAs/SM (two sync domains), CTA tile
// 128x128, warp tile 64x64 (MMA:LDSM = 32:8 — smem crossbar at ~94B/cyc,
// 27% headroom vs the saturated 125B/cyc of the 64x32 shape).
// ---------------------------------------------------------------------------
#define A_TILE  16384                 // 128 rows * 128B
#define B_TILE  16384
#define STAGE_SZ (A_TILE + B_TILE)    // 32768
#define SM_TOTAL (NSTAGE * STAGE_SZ)  // 98304 per CTA

#define PF 8

__device__ __forceinline__ void load_stage_A(uint32_t sb, int stage, int kc,
                                             int m0, int tid) {
    const __half* Ag = g_A + (size_t)m0 * K_DIM + kc * KC;
    uint32_t abase = sb + stage * STAGE_SZ;
#pragma unroll
    for (int it = 0; it < 8; it++) {                // A: 1024 16B units
        int u = tid + it * NTHREADS;
        int r = u >> 3, c = u & 7;
        uint32_t off = (uint32_t)(r * 128 + c * 16);
        cp_async16(abase + sw128(off), Ag + (size_t)r * K_DIM + c * 8);
    }
}

__device__ __forceinline__ void load_stage_B(uint32_t sb, int stage, int kc,
                                             int n0, int tid) {
    const __half* Bg = g_B + (size_t)n0 * K_DIM + kc * KC;
    uint32_t bbase = sb + stage * STAGE_SZ + A_TILE;
#pragma unroll
    for (int it = 0; it < 8; it++) {                // B: 1024 16B units
        int u = tid + it * NTHREADS;
        int r = u >> 3, c = u & 7;
        uint32_t off = (uint32_t)(r * 128 + c * 16);
        cp_async16(bbase + sw128(off), Bg + (size_t)r * K_DIM + c * 8);
    }
}

__global__ void __launch_bounds__(NTHREADS, 2) rin_fused_kernel(
        const int* __restrict__ ids, const float* __restrict__ emb,
        float* __restrict__ out, const float* __restrict__ bias) {
    extern __shared__ char smem[];
    const int tid = threadIdx.x;

    if (blockIdx.x < NSCAN) {
        // ---------------- scan producer (R9-proven logic) ----------------
        float* s_sin = (float*)smem;
        float* s_cos = s_sin + LUT_N;
        for (int i = tid; i < LUT_N; i += NTHREADS) {
            float g = __fmul_rn((float)i, GRID_F);
            s_sin[i] = sinf(g);
            s_cos[i] = cosf(g);
        }
        __syncthreads();
        if (tid >= 32) return;                 // only warp 0 runs chains

        const int bid = blockIdx.x;
        const int b = bid >> 3;
        const int d = ((bid & 7) << 5) + tid;

        const int* rid = ids + b * S_DIM;
        float hr = 0.0f, hi = 0.0f;

        float wp[PF], bp[PF];
#pragma unroll
        for (int j = 0; j < PF; j++) {
            int id = __ldg(rid + j);
            wp[j] = __ldg(emb + (size_t)id * K_DIM + d);
            bp[j] = __ldg(emb + (size_t)id * K_DIM + D_DIM + d);
        }

        __half* arow = g_A + (size_t)b * S_DIM * K_DIM + d;

        for (int s0 = 0; s0 < S_DIM; s0 += PF) {
#pragma unroll
            for (int j = 0; j < PF; j++) {
                int s = s0 + j;
                float w = wp[j];
                float bt = bp[j];
                if (s + PF < S_DIM) {
                    int id = __ldg(rid + s + PF);
                    wp[j] = __ldg(emb + (size_t)id * K_DIM + d);
                    bp[j] = __ldg(emb + (size_t)id * K_DIM + D_DIM + d);
                }
                float lam = __fadd_rn(1.0f, fabsf(w));
                float tp  = __fmul_rn((float)s, PHI_F);
                float tr  = __fadd_rn(__fadd_rn(div_rn_fast(hr, lam), bt), tp);
                float ti  = __fadd_rn(__fadd_rn(div_rn_fast(hi, lam), bt), tp);
                int ir = __float2int_rd(__fmul_rn(tr, CINV_F)) & (LUT_N - 1);
                int ii = __float2int_rd(__fmul_rn(ti, CINV_F)) & (LUT_N - 1);
                float sr = s_sin[ir], cr = s_cos[ir];
                float si = s_sin[ii], ci = s_cos[ii];
                float nhr = __fsub_rn(__fmul_rn(cr, ci), __fmul_rn(sr, si));
                float nhi = __fadd_rn(__fmul_rn(cr, si), __fmul_rn(sr, ci));
                hr = nhr;
                hi = nhi;
                arow[(size_t)s * K_DIM]         = __float2half_rn(nhr);
                arow[(size_t)s * K_DIM + D_DIM] = __float2half_rn(nhi);
            }
            if (((s0 + PF) & 127) == 0) {       // publish every 128 steps
                __threadfence();
                __syncwarp();
                if (tid == 0) st_rel(&g_prog[bid], s0 + PF);
            }
        }
        return;
    }

    // --------------------------- GEMM consumer ---------------------------
    uint32_t sb = smem_u32(smem);
    const int g = blockIdx.x - NSCAN;
    // step-major, batch-minor tile order: matches scan production order
    const int mt = g / NTILE_N;              // 0..63
    const int jj_step = mt >> 2;             // step group 0..15
    const int bb = mt & 3;                   // batch
    const int m0 = bb * S_DIM + jj_step * TM;
    const int n0 = (g % NTILE_N) * TN;
    const int lane = tid & 31;
    const int wid = tid >> 5;                // 0..3
    const int wm = wid & 1;                  // 2 M slabs of 64
    const int wn = wid >> 1;                 // 2 N slabs of 64

    // B is ready (stream-ordered): issue B transfers for stages 0,1 now so
    // they overlap the A-availability wait below.
    load_stage_B(sb, 0, 0, n0, tid);
    load_stage_B(sb, 1, 1, n0, tid);

    // wait until this tile's 128 A-rows are produced by all 8 scan blocks of bb
    {
        const int s_end = jj_step * TM + TM;
        if (tid < 8) {
            const int* fp = &g_prog[bb * 8 + tid];
            while (ld_acq(fp) < s_end) __nanosleep(128);
        }
        __syncthreads();
        // Bridge generic-proxy release chain (scan's st.global + fence) to the
        // async-proxy cp.async reads of g_A below.
        FENCE_PROXY_ASYNC();
    }

    float acc[4][8][4];
#pragma unroll
    for (int i = 0; i < 4; i++)
#pragma unroll
        for (int j = 0; j < 8; j++)
#pragma unroll
            for (int k = 0; k < 4; k++) acc[i][j][k] = 0.0f;

    load_stage_A(sb, 0, 0, m0, tid);
    CP_COMMIT();                    // group0 = {B0, B1, A0}
    load_stage_A(sb, 1, 1, m0, tid);
    CP_COMMIT();                    // group1 = {A1}

    const int a_row  = wm * 64 + (lane & 15);
    const int a_sega = (lane >> 4) * 16;
    const int b_row  = wn * 64 + (lane & 7) + ((lane >> 4) << 3);
    const int b_sega = ((lane >> 3) & 1) * 16;

    int buf = 0;
    for (int kc = 0; kc < NKC; kc++) {
        CP_WAIT1();                 // stage kc data complete
        __syncthreads();
        if (kc + 2 < NKC) {
            int st2 = (buf + 2 >= NSTAGE) ? buf + 2 - NSTAGE : buf + 2;
            load_stage_B(sb, st2, kc + 2, n0, tid);
            load_stage_A(sb, st2, kc + 2, m0, tid);
            CP_COMMIT();
        }

        const uint32_t abase = sb + buf * STAGE_SZ;
        const uint32_t bbase = abase + A_TILE;
#pragma unroll
        for (int ks = 0; ks < 4; ks++) {
            uint32_t ar[4][4];
#pragma unroll
            for (int i = 0; i < 4; i++) {
                uint32_t off = (uint32_t)((a_row + i * 16) * 128 + ks * 32 + a_sega);
                ldmatrix_x4(ar[i], abase + sw128(off));
            }
            uint32_t br[4][4];
#pragma unroll
            for (int j = 0; j < 4; j++) {
                uint32_t off = (uint32_t)((b_row + j * 16) * 128 + ks * 32 + b_sega);
                ldmatrix_x4(br[j], bbase + sw128(off));
            }
#pragma unroll
            for (int i = 0; i < 4; i++)
#pragma unroll
                for (int j2 = 0; j2 < 8; j2++)
                    mma16816(acc[i][j2], ar[i],
                             br[j2 >> 1][(j2 & 1) * 2],
                             br[j2 >> 1][(j2 & 1) * 2 + 1]);
        }
        buf = (buf + 1 == NSTAGE) ? 0 : buf + 1;
    }

    const int ncol0 = n0 + wn * 64;
#pragma unroll
    for (int i = 0; i < 4; i++) {
        int row = m0 + wm * 64 + i * 16 + (lane >> 2);
        float* o0 = out + (size_t)row * V_DIM + ncol0;
        float* o1 = o0 + (size_t)8 * V_DIM;
#pragma unroll
        for (int j2 = 0; j2 < 8; j2++) {
            int col = j2 * 8 + (lane & 3) * 2;
            float bx = __ldg(bias + ncol0 + col);
            float by = __ldg(bias + ncol0 + col + 1);
            float2 v0 = make_float2(acc[i][j2][0] + bx, acc[i][j2][1] + by);
            float2 v1 = make_float2(acc[i][j2][2] + bx, acc[i][j2][3] + by);
            *(float2*)(o0 + col) = v0;
            *(float2*)(o1 + col) = v1;
        }
    }
}

// ---------------------------------------------------------------------------
// launch
// ---------------------------------------------------------------------------
extern "C" void kernel_launch(void* const* d_in, const int* in_sizes, int n_in,
                              void* d_out, int out_size) {
    const int*   ids  = (const int*)d_in[0];
    const float* emb  = (const float*)d_in[1];
    const float* proj = (const float*)d_in[2];
    const float* bias = (const float*)d_in[3];
    float* out = (float*)d_out;

    cudaFuncSetAttribute(rin_fused_kernel,
                         cudaFuncAttributeMaxDynamicSharedMemorySize, SM_TOTAL);

    rin_conv_kernel<<<(V_DIM * K_DIM / 4 + 255) / 256, 256>>>(proj);
    rin_fused_kernel<<<NSCAN + NTILE_M * NTILE_N, NTHREADS, SM_TOTAL>>>(
        ids, emb, out, bias);
}

// round 16
// speedup vs baseline: 1.2448x; 1.0336x over previous
#include <cuda_runtime.h>
#include <cuda_fp16.h>
#include <cstdint>
#include <cstddef>

// ---------------------------------------------------------------------------
// Problem constants
// ---------------------------------------------------------------------------
#define B_DIM 4
#define S_DIM 2048
#define V_DIM 32000
#define K_DIM 512            // 2*D
#define D_DIM 256
#define M_DIM 8192           // B*S
#define LUT_N 4096

// exact-double constants rounded to f32
#define PHI_F   1.6180339887498949f          // (1+sqrt5)/2
#define CINV_F  651.8986469044033f           // 4096 / (2*pi)
#define GRID_F  0.0015339807878856412f       // (2*pi) / 4096

// GEMM tiling: CTA tile 128x128, 128 threads (4 warps), warp tile 64x64
#define TM 128
#define TN 128
#define KC 64                // k elements per stage = 128 bytes fp16
#define NKC 8                // 512 / 64
#define NSTAGE 3
#define NTHREADS 128

#define NSCAN 32             // scan blocks (8 per batch, 32 chains each)
#define NTILE_N (V_DIM / TN) // 250
#define NTILE_M (M_DIM / TM) // 64

// scratch (device globals allowed; runtime alloc is not)
static __device__ __align__(256) __half g_A[(size_t)M_DIM * K_DIM];
static __device__ __align__(256) __half g_B[(size_t)V_DIM * K_DIM];
static __device__ int g_prog[NSCAN];   // per-scan-block step progress

// ---------------------------------------------------------------------------
// PTX helpers (base-arch only: cp.async, ldmatrix, mma.sync)
// ---------------------------------------------------------------------------
__device__ __forceinline__ uint32_t smem_u32(const void* p) {
    return (uint32_t)__cvta_generic_to_shared(p);
}
__device__ __forceinline__ void cp_async16(uint32_t dst, const void* src) {
    asm volatile("cp.async.cg.shared.global [%0], [%1], 16;"
                 :: "r"(dst), "l"(src) : "memory");
}
#define CP_COMMIT() asm volatile("cp.async.commit_group;" ::: "memory")
#define CP_WAIT1()  asm volatile("cp.async.wait_group 1;" ::: "memory")
#define FENCE_PROXY_ASYNC() asm volatile("fence.proxy.async;" ::: "memory")

__device__ __forceinline__ void ldmatrix_x4(uint32_t* r, uint32_t addr) {
    asm volatile("ldmatrix.sync.aligned.m8n8.x4.shared.b16 {%0,%1,%2,%3}, [%4];"
                 : "=r"(r[0]), "=r"(r[1]), "=r"(r[2]), "=r"(r[3]) : "r"(addr));
}

__device__ __forceinline__ void mma16816(float* c, const uint32_t* a,
                                         uint32_t b0, uint32_t b1) {
    asm volatile(
        "mma.sync.aligned.m16n8k16.row.col.f32.f16.f16.f32 "
        "{%0,%1,%2,%3}, {%4,%5,%6,%7}, {%8,%9}, {%0,%1,%2,%3};"
        : "+f"(c[0]), "+f"(c[1]), "+f"(c[2]), "+f"(c[3])
        : "r"(a[0]), "r"(a[1]), "r"(a[2]), "r"(a[3]), "r"(b0), "r"(b1));
}

__device__ __forceinline__ uint32_t sw128(uint32_t off) {
    return off ^ ((off >> 3) & 0x70);
}

__device__ __forceinline__ int ld_acq(const int* p) {
    int v;
    asm volatile("ld.acquire.gpu.global.b32 %0, [%1];" : "=r"(v) : "l"(p));
    return v;
}
__device__ __forceinline__ void st_rel(int* p, int v) {
    asm volatile("st.release.gpu.global.b32 [%0], %1;" :: "l"(p), "r"(v) : "memory");
}

// Guard-free correctly-rounded fp32 division (Markstein). Valid for normal
// a, b with no overflow in intermediates — here |a|<=1, b in [1, ~3].
__device__ __forceinline__ float div_rn_fast(float a, float b) {
    float r;
    asm("rcp.approx.f32 %0, %1;" : "=f"(r) : "f"(b));
    float e = __fmaf_rn(-b, r, 1.0f);
    r = __fmaf_rn(r, e, r);
    e = __fmaf_rn(-b, r, 1.0f);
    r = __fmaf_rn(r, e, r);
    float q = __fmul_rn(a, r);
    float rem = __fmaf_rn(-b, q, a);
    return __fmaf_rn(rem, r, q);
}

// ---------------------------------------------------------------------------
// Kernel A: proj fp32 -> fp16, plus progress-flag reset (runs before fused)
// ---------------------------------------------------------------------------
__global__ void rin_conv_kernel(const float* __restrict__ p) {
    if (blockIdx.x == 0 && threadIdx.x < NSCAN) g_prog[threadIdx.x] = 0;
    size_t i = ((size_t)blockIdx.x * blockDim.x + threadIdx.x) * 4;
    if (i < (size_t)V_DIM * K_DIM) {
        float4 v = *(const float4*)(p + i);
        __half2 h0 = __floats2half2_rn(v.x, v.y);
        __half2 h1 = __floats2half2_rn(v.z, v.w);
        uint2 st;
        st.x = *(uint32_t*)&h0;
        st.y = *(uint32_t*)&h1;
        *(uint2*)(g_B + i) = st;
    }
}

// ---------------------------------------------------------------------------
// Fused kernel: bids 0..31 = scan producers (R9-proven logic), bids 32.. =
// GEMM consumers. 128 threads/CTA, 2 CTAs/SM, CTA tile 128x128, warp tile
// 64x64. Next-stage cp.async issue is spread across the 4 ks iterations and
// placed in the LDSM->MMA latency window (LSU burst smoothing).
// ---------------------------------------------------------------------------
#define A_TILE  16384                 // 128 rows * 128B
#define B_TILE  16384
#define STAGE_SZ (A_TILE + B_TILE)    // 32768
#define SM_TOTAL (NSTAGE * STAGE_SZ)  // 98304 per CTA

#define PF 8

// Issue 4 of the 16 per-stage load iterations (2 A + 2 B) for slice ks.
__device__ __forceinline__ void load_stage_slice(uint32_t sb, int stage, int kc,
                                                 int m0, int n0, int tid, int ks) {
    const __half* Ag = g_A + (size_t)m0 * K_DIM + kc * KC;
    const __half* Bg = g_B + (size_t)n0 * K_DIM + kc * KC;
    uint32_t abase = sb + stage * STAGE_SZ;
    uint32_t bbase = abase + A_TILE;
#pragma unroll
    for (int it = 2 * ks; it < 2 * ks + 2; it++) {
        int u = tid + it * NTHREADS;           // A: 1024 16B units total
        int r = u >> 3, c = u & 7;
        uint32_t off = (uint32_t)(r * 128 + c * 16);
        cp_async16(abase + sw128(off), Ag + (size_t)r * K_DIM + c * 8);
    }
#pragma unroll
    for (int it = 2 * ks; it < 2 * ks + 2; it++) {
        int u = tid + it * NTHREADS;           // B: 1024 16B units total
        int r = u >> 3, c = u & 7;
        uint32_t off = (uint32_t)(r * 128 + c * 16);
        cp_async16(bbase + sw128(off), Bg + (size_t)r * K_DIM + c * 8);
    }
}

__device__ __forceinline__ void load_stage_full(uint32_t sb, int stage, int kc,
                                                int m0, int n0, int tid) {
#pragma unroll
    for (int ks = 0; ks < 4; ks++)
        load_stage_slice(sb, stage, kc, m0, n0, tid, ks);
}

__device__ __forceinline__ void load_stage_B_only(uint32_t sb, int stage, int kc,
                                                  int n0, int tid) {
    const __half* Bg = g_B + (size_t)n0 * K_DIM + kc * KC;
    uint32_t bbase = sb + stage * STAGE_SZ + A_TILE;
#pragma unroll
    for (int it = 0; it < 8; it++) {
        int u = tid + it * NTHREADS;
        int r = u >> 3, c = u & 7;
        uint32_t off = (uint32_t)(r * 128 + c * 16);
        cp_async16(bbase + sw128(off), Bg + (size_t)r * K_DIM + c * 8);
    }
}

__device__ __forceinline__ void load_stage_A_only(uint32_t sb, int stage, int kc,
                                                  int m0, int tid) {
    const __half* Ag = g_A + (size_t)m0 * K_DIM + kc * KC;
    uint32_t abase = sb + stage * STAGE_SZ;
#pragma unroll
    for (int it = 0; it < 8; it++) {
        int u = tid + it * NTHREADS;
        int r = u >> 3, c = u & 7;
        uint32_t off = (uint32_t)(r * 128 + c * 16);
        cp_async16(abase + sw128(off), Ag + (size_t)r * K_DIM + c * 8);
    }
}

__global__ void __launch_bounds__(NTHREADS, 2) rin_fused_kernel(
        const int* __restrict__ ids, const float* __restrict__ emb,
        float* __restrict__ out, const float* __restrict__ bias) {
    extern __shared__ char smem[];
    const int tid = threadIdx.x;

    if (blockIdx.x < NSCAN) {
        // ---------------- scan producer (R9-proven logic) ----------------
        float* s_sin = (float*)smem;
        float* s_cos = s_sin + LUT_N;
        for (int i = tid; i < LUT_N; i += NTHREADS) {
            float g = __fmul_rn((float)i, GRID_F);
            s_sin[i] = sinf(g);
            s_cos[i] = cosf(g);
        }
        __syncthreads();
        if (tid >= 32) return;                 // only warp 0 runs chains

        const int bid = blockIdx.x;
        const int b = bid >> 3;
        const int d = ((bid & 7) << 5) + tid;

        const int* rid = ids + b * S_DIM;
        float hr = 0.0f, hi = 0.0f;

        float wp[PF], bp[PF];
#pragma unroll
        for (int j = 0; j < PF; j++) {
            int id = __ldg(rid + j);
            wp[j] = __ldg(emb + (size_t)id * K_DIM + d);
            bp[j] = __ldg(emb + (size_t)id * K_DIM + D_DIM + d);
        }

        __half* arow = g_A + (size_t)b * S_DIM * K_DIM + d;

        for (int s0 = 0; s0 < S_DIM; s0 += PF) {
#pragma unroll
            for (int j = 0; j < PF; j++) {
                int s = s0 + j;
                float w = wp[j];
                float bt = bp[j];
                if (s + PF < S_DIM) {
                    int id = __ldg(rid + s + PF);
                    wp[j] = __ldg(emb + (size_t)id * K_DIM + d);
                    bp[j] = __ldg(emb + (size_t)id * K_DIM + D_DIM + d);
                }
                float lam = __fadd_rn(1.0f, fabsf(w));
                float tp  = __fmul_rn((float)s, PHI_F);
                float tr  = __fadd_rn(__fadd_rn(div_rn_fast(hr, lam), bt), tp);
                float ti  = __fadd_rn(__fadd_rn(div_rn_fast(hi, lam), bt), tp);
                int ir = __float2int_rd(__fmul_rn(tr, CINV_F)) & (LUT_N - 1);
                int ii = __float2int_rd(__fmul_rn(ti, CINV_F)) & (LUT_N - 1);
                float sr = s_sin[ir], cr = s_cos[ir];
                float si = s_sin[ii], ci = s_cos[ii];
                float nhr = __fsub_rn(__fmul_rn(cr, ci), __fmul_rn(sr, si));
                float nhi = __fadd_rn(__fmul_rn(cr, si), __fmul_rn(sr, ci));
                hr = nhr;
                hi = nhi;
                arow[(size_t)s * K_DIM]         = __float2half_rn(nhr);
                arow[(size_t)s * K_DIM + D_DIM] = __float2half_rn(nhi);
            }
            if (((s0 + PF) & 127) == 0) {       // publish every 128 steps
                __threadfence();
                __syncwarp();
                if (tid == 0) st_rel(&g_prog[bid], s0 + PF);
            }
        }
        return;
    }

    // --------------------------- GEMM consumer ---------------------------
    uint32_t sb = smem_u32(smem);
    const int g = blockIdx.x - NSCAN;
    // step-major, batch-minor tile order: matches scan production order
    const int mt = g / NTILE_N;              // 0..63
    const int jj_step = mt >> 2;             // step group 0..15
    const int bb = mt & 3;                   // batch
    const int m0 = bb * S_DIM + jj_step * TM;
    const int n0 = (g % NTILE_N) * TN;
    const int lane = tid & 31;
    const int wid = tid >> 5;                // 0..3
    const int wm = wid & 1;                  // 2 M slabs of 64
    const int wn = wid >> 1;                 // 2 N slabs of 64

    // B is ready (stream-ordered): issue B transfers for stages 0,1 now so
    // they overlap the A-availability wait below.
    load_stage_B_only(sb, 0, 0, n0, tid);
    load_stage_B_only(sb, 1, 1, n0, tid);

    // wait until this tile's 128 A-rows are produced by all 8 scan blocks of bb
    {
        const int s_end = jj_step * TM + TM;
        if (tid < 8) {
            const int* fp = &g_prog[bb * 8 + tid];
            while (ld_acq(fp) < s_end) __nanosleep(128);
        }
        __syncthreads();
        // Bridge generic-proxy release chain (scan's st.global + fence) to the
        // async-proxy cp.async reads of g_A below.
        FENCE_PROXY_ASYNC();
    }

    float acc[4][8][4];
#pragma unroll
    for (int i = 0; i < 4; i++)
#pragma unroll
        for (int j = 0; j < 8; j++)
#pragma unroll
            for (int k = 0; k < 4; k++) acc[i][j][k] = 0.0f;

    load_stage_A_only(sb, 0, 0, m0, tid);
    CP_COMMIT();                    // group0 = {B0, B1, A0}
    load_stage_A_only(sb, 1, 1, m0, tid);
    CP_COMMIT();                    // group1 = {A1}

    const int a_row  = wm * 64 + (lane & 15);
    const int a_sega = (lane >> 4) * 16;
    const int b_row  = wn * 64 + (lane & 7) + ((lane >> 4) << 3);
    const int b_sega = ((lane >> 3) & 1) * 16;

    int buf = 0;
    for (int kc = 0; kc < NKC; kc++) {
        CP_WAIT1();                 // stage kc data complete
        __syncthreads();
        const int do_load = (kc + 2 < NKC);
        const int st2 = (buf + 2 >= NSTAGE) ? buf + 2 - NSTAGE : buf + 2;

        const uint32_t abase = sb + buf * STAGE_SZ;
        const uint32_t bbase = abase + A_TILE;
#pragma unroll
        for (int ks = 0; ks < 4; ks++) {
            uint32_t ar[4][4];
#pragma unroll
            for (int i = 0; i < 4; i++) {
                uint32_t off = (uint32_t)((a_row + i * 16) * 128 + ks * 32 + a_sega);
                ldmatrix_x4(ar[i], abase + sw128(off));
            }
            uint32_t br[4][4];
#pragma unroll
            for (int j = 0; j < 4; j++) {
                uint32_t off = (uint32_t)((b_row + j * 16) * 128 + ks * 32 + b_sega);
                ldmatrix_x4(br[j], bbase + sw128(off));
            }
            // fill the LDSM->MMA latency window with next-stage load issue
            if (do_load)
                load_stage_slice(sb, st2, kc + 2, m0, n0, tid, ks);
#pragma unroll
            for (int i = 0; i < 4; i++)
#pragma unroll
                for (int j2 = 0; j2 < 8; j2++)
                    mma16816(acc[i][j2], ar[i],
                             br[j2 >> 1][(j2 & 1) * 2],
                             br[j2 >> 1][(j2 & 1) * 2 + 1]);
        }
        CP_COMMIT();                // one group per stage (empty near tail)
        buf = (buf + 1 == NSTAGE) ? 0 : buf + 1;
    }

    const int ncol0 = n0 + wn * 64;
#pragma unroll
    for (int i = 0; i < 4; i++) {
        int row = m0 + wm * 64 + i * 16 + (lane >> 2);
        float* o0 = out + (size_t)row * V_DIM + ncol0;
        float* o1 = o0 + (size_t)8 * V_DIM;
#pragma unroll
        for (int j2 = 0; j2 < 8; j2++) {
            int col = j2 * 8 + (lane & 3) * 2;
            float bx = __ldg(bias + ncol0 + col);
            float by = __ldg(bias + ncol0 + col + 1);
            float2 v0 = make_float2(acc[i][j2][0] + bx, acc[i][j2][1] + by);
            float2 v1 = make_float2(acc[i][j2][2] + bx, acc[i][j2][3] + by);
            *(float2*)(o0 + col) = v0;
            *(float2*)(o1 + col) = v1;
        }
    }
}

// ---------------------------------------------------------------------------
// launch
// ---------------------------------------------------------------------------
extern "C" void kernel_launch(void* const* d_in, const int* in_sizes, int n_in,
                              void* d_out, int out_size) {
    const int*   ids  = (const int*)d_in[0];
    const float* emb  = (const float*)d_in[1];
    const float* proj = (const float*)d_in[2];
    const float* bias = (const float*)d_in[3];
    float* out = (float*)d_out;

    cudaFuncSetAttribute(rin_fused_kernel,
                         cudaFuncAttributeMaxDynamicSharedMemorySize, SM_TOTAL);

    rin_conv_kernel<<<(V_DIM * K_DIM / 4 + 255) / 256, 256>>>(proj);
    rin_fused_kernel<<<NSCAN + NTILE_M * NTILE_N, NTHREADS, SM_TOTAL>>>(
        ids, emb, out, bias);
}